// round 6
// baseline (speedup 1.0000x reference)
#include <cuda_runtime.h>
#include <cstdint>
#include <math.h>

#define BB 64
#define TT 512
#define DD 512
#define UU 1024
#define G4 4096   // 4*UU
#define NBLK 128
#define NTHR 256

// Scratch (allocation-free rule: __device__ globals)
__device__ float g_xg[(size_t)TT * NBLK * 2048];   // [t][blk][g][b*8+j]  512MB
__device__ float g_xtf[(size_t)BB * TT * DD];      // tf32-rounded x      64MB
__device__ float g_Wxtf[(size_t)DD * G4];          // tf32-rounded Wx      8MB
__device__ float g_h[2 * BB * UU];                 // ping-pong h
__device__ unsigned g_flag[NBLK];                  // per-block completed-step count

// ---------- helpers ----------
__device__ __forceinline__ unsigned f2tf(float x) {
    unsigned r;
    asm volatile("cvt.rna.tf32.f32 %0, %1;" : "=r"(r) : "f"(x));
    return r;
}
__device__ __forceinline__ float tfbits(float x) { return __uint_as_float(f2tf(x)); }
__device__ __forceinline__ unsigned fu(float x) { return __float_as_uint(x); }

__device__ __forceinline__ void mma_tf32(float d[4], const unsigned a[4], unsigned b0, unsigned b1) {
    asm volatile(
        "mma.sync.aligned.m16n8k8.row.col.f32.tf32.tf32.f32 "
        "{%0,%1,%2,%3}, {%4,%5,%6,%7}, {%8,%9}, {%0,%1,%2,%3};"
        : "+f"(d[0]), "+f"(d[1]), "+f"(d[2]), "+f"(d[3])
        : "r"(a[0]), "r"(a[1]), "r"(a[2]), "r"(a[3]), "r"(b0), "r"(b1));
}

__device__ __forceinline__ float fsig(float z) { return 1.f / (1.f + __expf(-z)); }
__device__ __forceinline__ float ftanh(float z) { return 2.f / (1.f + __expf(-2.f * z)) - 1.f; }

__device__ __forceinline__ void cp_async16(uint32_t s, const float* g) {
    asm volatile("cp.async.cg.shared.global [%0], [%1], 16;\n" :: "r"(s), "l"(g));
}
#define CP_COMMIT() asm volatile("cp.async.commit_group;\n" ::: "memory")
#define CP_WAIT(N)  asm volatile("cp.async.wait_group %0;\n" :: "n"(N) : "memory")

__device__ __forceinline__ unsigned ld_acq(const unsigned* p) {
    unsigned v;
    asm volatile("ld.acquire.gpu.global.u32 %0, [%1];" : "=r"(v) : "l"(p));
    return v;
}
__device__ __forceinline__ void st_rel(unsigned* p, unsigned v) {
    asm volatile("st.release.gpu.global.u32 [%0], %1;" :: "l"(p), "r"(v));
}

// ---------- Kernel 1: prep — tf32-round x, Wx; round h0 into g_h; clear flags ----------
__global__ void __launch_bounds__(256) prep(const float* __restrict__ x,
                                            const float* __restrict__ Wx,
                                            const float* __restrict__ h0) {
    size_t i = (size_t)blockIdx.x * 256 + threadIdx.x;
    if (i < (size_t)BB * TT * DD) g_xtf[i] = tfbits(x[i]);
    if (i < (size_t)DD * G4)      g_Wxtf[i] = tfbits(Wx[i]);
    if (i < (size_t)BB * UU)      g_h[i] = tfbits(h0[i]);
    if (i < NBLK)                 g_flag[i] = 0;
}

// ---------- Kernel 2: xg = x @ Wx + b (tf32 mma, 4-stage cp.async) ----------
// BM=128, BN=64, BK=32, 256 threads. Output layout [t][blk][g][b*8+j].
#define XA_ST 4608   // 128*36 floats per A stage
#define XB_ST 2176   // 32*68 floats per B stage
__global__ void __launch_bounds__(256, 2) xg_kernel(const float* __restrict__ bias) {
    extern __shared__ float sm[];
    float* As = sm;                 // 4 stages
    float* Bs = sm + 4 * XA_ST;     // 4 stages

    const int tid  = threadIdx.x;
    const int w    = tid >> 5;
    const int lane = tid & 31;
    const int gid  = lane >> 2;
    const int tig  = lane & 3;
    const int wm   = w >> 1;        // 0..3 : rows wm*32
    const int wn   = w & 1;         // 0..1 : cols wn*32

    const int m0 = blockIdx.y * 128;
    const int c0 = blockIdx.x * 64;

    const uint32_t as_base = (uint32_t)__cvta_generic_to_shared(As);
    const uint32_t bs_base = (uint32_t)__cvta_generic_to_shared(Bs);

    float acc[2][4][4];
#pragma unroll
    for (int mi = 0; mi < 2; mi++)
#pragma unroll
        for (int ni = 0; ni < 4; ni++)
#pragma unroll
            for (int j = 0; j < 4; j++) acc[mi][ni][j] = 0.f;

    // issue chunk kc into stage s
    auto issue = [&](int kc, int s) {
#pragma unroll
        for (int i = 0; i < 4; i++) {
            int id = tid + i * 256;             // 0..1023
            int row = id >> 3;
            int k4  = (id & 7) * 4;
            cp_async16(as_base + (uint32_t)((s * XA_ST + row * 36 + k4) * 4),
                       g_xtf + (size_t)(m0 + row) * DD + kc * 32 + k4);
        }
#pragma unroll
        for (int i = 0; i < 2; i++) {
            int id = tid + i * 256;             // 0..511
            int k  = id >> 4;
            int n4 = (id & 15) * 4;
            cp_async16(bs_base + (uint32_t)((s * XB_ST + k * 68 + n4) * 4),
                       g_Wxtf + (size_t)(kc * 32 + k) * G4 + c0 + n4);
        }
    };

    issue(0, 0); CP_COMMIT();
    issue(1, 1); CP_COMMIT();
    issue(2, 2); CP_COMMIT();

    for (int kc = 0; kc < 16; kc++) {
        CP_WAIT(2);
        __syncthreads();
        if (kc + 3 < 16) issue(kc + 3, (kc + 3) & 3);
        CP_COMMIT();

        const float* A = As + (kc & 3) * XA_ST;
        const float* B = Bs + (kc & 3) * XB_ST;
#pragma unroll
        for (int q = 0; q < 4; q++) {
            const int kk = q * 8 + tig;
            unsigned a[2][4];
#pragma unroll
            for (int mi = 0; mi < 2; mi++) {
                int r0 = wm * 32 + mi * 16 + gid;
                a[mi][0] = fu(A[r0 * 36 + kk]);
                a[mi][1] = fu(A[(r0 + 8) * 36 + kk]);
                a[mi][2] = fu(A[r0 * 36 + kk + 4]);
                a[mi][3] = fu(A[(r0 + 8) * 36 + kk + 4]);
            }
#pragma unroll
            for (int ni = 0; ni < 4; ni++) {
                int cb = wn * 32 + ni * 8 + gid;
                unsigned b0 = fu(B[kk * 68 + cb]);
                unsigned b1 = fu(B[(kk + 4) * 68 + cb]);
#pragma unroll
                for (int mi = 0; mi < 2; mi++) mma_tf32(acc[mi][ni], a[mi], b0, b1);
            }
        }
    }

    // epilogue: +bias, scatter to [t][blk][g][b*8+j]
#pragma unroll
    for (int mi = 0; mi < 2; mi++) {
#pragma unroll
        for (int ni = 0; ni < 4; ni++) {
#pragma unroll
            for (int j = 0; j < 4; j++) {
                int m   = m0 + wm * 32 + mi * 16 + gid + ((j >= 2) ? 8 : 0);
                int col = c0 + wn * 32 + ni * 8 + tig * 2 + (j & 1);
                float v = acc[mi][ni][j] + bias[col];
                int b   = m >> 9;        // batch
                int t   = m & (TT - 1);  // time
                int g   = col >> 10;     // gate
                int u   = col & (UU - 1);
                int blk = u >> 3;
                int jj  = u & 7;
                g_xg[((size_t)t * NBLK + blk) * 2048 + g * 512 + b * 8 + jj] = v;
            }
        }
    }
}

// ---------- Kernel 3: persistent LSTM ----------
// 128 blocks x 256 threads, 1 block/SM. Block owns u-cols u0..u0+7, all 4 gates.
// Wh slice SMEM-resident (pre-swizzled tf32 B-fragments). c in registers.
// h ping-pong via L2; 3-deep cp.async; release/acquire flags; xg via reg prefetch.
__global__ void __launch_bounds__(NTHR, 1) lstm_persistent(const float* __restrict__ Wh,
                                                           const float* __restrict__ c0,
                                                           float* __restrict__ out) {
    extern __shared__ float smem[];
    float* FB = smem;                 // 32768 f: B-fragments
    float* HS = FB + 32768;           // 4 * 64*68 f: h staging
    float* GM = HS + 4 * 64 * 68;     // 64*33 f: gate exchange

    const int tid  = threadIdx.x;
    const int w    = tid >> 5;
    const int lane = tid & 31;
    const int gid  = lane >> 2;
    const int tig  = lane & 3;
    const int wm   = w & 3;
    const int wn   = w >> 2;
    const int blk  = blockIdx.x;
    const int u0   = blk * 8;

    // one-time: Wh fragments (tf32, pre-swizzled)
    for (int idx = tid; idx < 32768; idx += NTHR) {
        int e     = idx & 7;
        int ln    = (idx >> 3) & 31;
        int tile  = (idx >> 8) & 3;
        int kcc32 = idx >> 10;
        int q     = e >> 1;
        int pair  = e & 1;
        int lgid  = ln >> 2;
        int ltig  = ln & 3;
        int k     = kcc32 * 32 + q * 8 + ltig + pair * 4;
        FB[idx] = tfbits(Wh[(size_t)k * G4 + tile * UU + u0 + lgid]);
    }

    float creg[2];
#pragma unroll
    for (int i = 0; i < 2; i++) {
        int e = tid + i * NTHR;
        int row = e >> 3, j = e & 7;
        creg[i] = c0[(size_t)row * UU + u0 + j];
    }
    __syncthreads();

    const float4* FB4 = reinterpret_cast<const float4*>(FB);
    const uint32_t hs_base = (uint32_t)__cvta_generic_to_shared(HS);
    const int r0 = wm * 16 + gid;
    const int t0i = wn * 2, t1i = wn * 2 + 1;

    for (int t = 0; t < TT; t++) {
        const float* h_in = g_h + (size_t)(t & 1) * BB * UU;
        float* h_out      = g_h + (size_t)((t + 1) & 1) * BB * UU;
        const float* xgt  = g_xg + ((size_t)t * NBLK + blk) * 2048;

        // wait for all producers of h_t
        if (t > 0 && tid < NBLK) {
            while (ld_acq(&g_flag[tid]) < (unsigned)t) { }
        }
        __syncthreads();

        float acc0[4] = {0.f, 0.f, 0.f, 0.f};
        float acc1[4] = {0.f, 0.f, 0.f, 0.f};

        // prologue: chunks 0..2 (3 groups in flight)
#pragma unroll
        for (int p = 0; p <= 2; p++) {
#pragma unroll
            for (int i = 0; i < 4; i++) {
                int id = tid + i * NTHR;
                int row = id >> 4, kq = id & 15;
                cp_async16(hs_base + (uint32_t)((p * 4352 + row * 68 + kq * 4) * 4),
                           h_in + (size_t)row * UU + p * 64 + kq * 4);
            }
            CP_COMMIT();
        }

        // xg prefetch into registers (coalesced LDG, latency hidden under k-loop)
        float xr[8];
#pragma unroll
        for (int i = 0; i < 2; i++)
#pragma unroll
            for (int g = 0; g < 4; g++)
                xr[i * 4 + g] = __ldg(xgt + g * 512 + tid + i * NTHR);

        for (int kcc = 0; kcc < 16; kcc++) {
            CP_WAIT(2);
            __syncthreads();

            if (kcc + 3 < 16) {
                int c = kcc + 3;
                int buf = c & 3;
#pragma unroll
                for (int i = 0; i < 4; i++) {
                    int id = tid + i * NTHR;
                    int row = id >> 4, kq = id & 15;
                    cp_async16(hs_base + (uint32_t)((buf * 4352 + row * 68 + kq * 4) * 4),
                               h_in + (size_t)row * UU + c * 64 + kq * 4);
                }
            }
            CP_COMMIT();

            const float* hb = HS + (kcc & 3) * 4352;
#pragma unroll
            for (int sub = 0; sub < 2; sub++) {
                const int kcc32 = kcc * 2 + sub;
                float4 bA0 = FB4[((kcc32 * 4 + t0i) * 32 + lane) * 2 + 0];
                float4 bA1 = FB4[((kcc32 * 4 + t0i) * 32 + lane) * 2 + 1];
                float4 bB0 = FB4[((kcc32 * 4 + t1i) * 32 + lane) * 2 + 0];
                float4 bB1 = FB4[((kcc32 * 4 + t1i) * 32 + lane) * 2 + 1];
#pragma unroll
                for (int q = 0; q < 4; q++) {
                    const int kk = sub * 32 + q * 8 + tig;
                    unsigned a[4];
                    a[0] = fu(hb[r0 * 68 + kk]);
                    a[1] = fu(hb[(r0 + 8) * 68 + kk]);
                    a[2] = fu(hb[r0 * 68 + kk + 4]);
                    a[3] = fu(hb[(r0 + 8) * 68 + kk + 4]);
                    unsigned b0a, b1a, b0b, b1b;
                    if (q == 0)      { b0a = fu(bA0.x); b1a = fu(bA0.y); b0b = fu(bB0.x); b1b = fu(bB0.y); }
                    else if (q == 1) { b0a = fu(bA0.z); b1a = fu(bA0.w); b0b = fu(bB0.z); b1b = fu(bB0.w); }
                    else if (q == 2) { b0a = fu(bA1.x); b1a = fu(bA1.y); b0b = fu(bB1.x); b1b = fu(bB1.y); }
                    else             { b0a = fu(bA1.z); b1a = fu(bA1.w); b0b = fu(bB1.z); b1b = fu(bB1.w); }
                    mma_tf32(acc0, a, b0a, b1a);
                    mma_tf32(acc1, a, b0b, b1b);
                }
            }
        }
        __syncthreads();

        // gate exchange
#pragma unroll
        for (int j = 0; j < 4; j++) {
            int row = wm * 16 + gid + ((j >> 1) ? 8 : 0);
            GM[row * 33 + t0i * 8 + tig * 2 + (j & 1)] = acc0[j];
            GM[row * 33 + t1i * 8 + tig * 2 + (j & 1)] = acc1[j];
        }
        __syncthreads();

        // epilogue: gates + c/h update (xg from registers)
#pragma unroll
        for (int i = 0; i < 2; i++) {
            int e = tid + i * NTHR;
            int row = e >> 3, j = e & 7;
            float zi = GM[row * 33 + 0 * 8 + j] + xr[i * 4 + 0];
            float zf = GM[row * 33 + 1 * 8 + j] + xr[i * 4 + 1];
            float zg = GM[row * 33 + 2 * 8 + j] + xr[i * 4 + 2];
            float zo = GM[row * 33 + 3 * 8 + j] + xr[i * 4 + 3];

            float ig = fsig(zi);
            float fg = fsig(zf);
            float gg = ftanh(zg);
            float og = fsig(zo);

            creg[i] = fg * creg[i] + ig * gg;
            float hv = og * ftanh(creg[i]);
            if (t == TT - 1) out[(size_t)row * UU + u0 + j] = hv;
            else             h_out[(size_t)row * UU + u0 + j] = tfbits(hv);
        }

        // publish completion (release store; no consumer for the last step)
        __syncthreads();
        if (t + 1 < TT && tid == 0) {
            st_rel(&g_flag[blk], (unsigned)(t + 1));
        }
    }
}

// ---------- launch (exactly 3 kernels: prep, xg, lstm) ----------
extern "C" void kernel_launch(void* const* d_in, const int* in_sizes, int n_in,
                              void* d_out, int out_size) {
    const float *x = nullptr, *h0 = nullptr, *c0 = nullptr;
    const float *Wx = nullptr, *Wh = nullptr, *bias = nullptr;
    for (int i = 0; i < n_in; i++) {
        const int s = in_sizes[i];
        const float* p = (const float*)d_in[i];
        if      (s == BB * TT * DD) x = p;
        else if (s == DD * G4)      Wx = p;
        else if (s == UU * G4)      Wh = p;
        else if (s == G4)           bias = p;
        else if (s == BB * UU)      { if (!h0) h0 = p; else c0 = p; }
    }

    const int XG_SMEM   = (4 * XA_ST + 4 * XB_ST) * 4;              // 108544
    const int LSTM_SMEM = (32768 + 4 * 64 * 68 + 64 * 33) * 4;      // 208896

    static bool attr_set = false;
    if (!attr_set) {
        cudaFuncSetAttribute(xg_kernel,
                             cudaFuncAttributeMaxDynamicSharedMemorySize, XG_SMEM);
        cudaFuncSetAttribute(lstm_persistent,
                             cudaFuncAttributeMaxDynamicSharedMemorySize, LSTM_SMEM);
        attr_set = true;
    }

    prep<<<(BB * TT * DD + 255) / 256, 256>>>(x, Wx, h0);
    xg_kernel<<<dim3(G4 / 64, (BB * TT) / 128), 256, XG_SMEM>>>(bias);
    lstm_persistent<<<NBLK, NTHR, LSTM_SMEM>>>(Wh, c0, (float*)d_out);
}

// round 7
// speedup vs baseline: 1.1070x; 1.1070x over previous
#include <cuda_runtime.h>
#include <cstdint>
#include <math.h>

#define BB 64
#define TT 512
#define DD 512
#define UU 1024
#define G4 4096   // 4*UU
#define NBLK 128
#define NTHR 256

// Scratch (allocation-free rule: __device__ globals)
__device__ float g_xg[(size_t)TT * NBLK * BB * 32];  // [t][blk][row][g*8+j] = 512MB
__device__ float g_h[2 * BB * UU];                   // ping-pong h (tf32-rounded)
__device__ unsigned g_flag[NBLK];                    // per-block completed-step count

// ---------- helpers ----------
__device__ __forceinline__ unsigned f2tf(float x) {
    unsigned r;
    asm volatile("cvt.rna.tf32.f32 %0, %1;" : "=r"(r) : "f"(x));
    return r;
}
__device__ __forceinline__ float tfbits(float x) { return __uint_as_float(f2tf(x)); }
__device__ __forceinline__ unsigned fu(float x) { return __float_as_uint(x); }

__device__ __forceinline__ void mma_tf32(float d[4], const unsigned a[4], unsigned b0, unsigned b1) {
    asm volatile(
        "mma.sync.aligned.m16n8k8.row.col.f32.tf32.tf32.f32 "
        "{%0,%1,%2,%3}, {%4,%5,%6,%7}, {%8,%9}, {%0,%1,%2,%3};"
        : "+f"(d[0]), "+f"(d[1]), "+f"(d[2]), "+f"(d[3])
        : "r"(a[0]), "r"(a[1]), "r"(a[2]), "r"(a[3]), "r"(b0), "r"(b1));
}

__device__ __forceinline__ float fsig(float z) { return 1.f / (1.f + __expf(-z)); }
__device__ __forceinline__ float ftanh(float z) { return 2.f / (1.f + __expf(-2.f * z)) - 1.f; }

__device__ __forceinline__ void cp_async16(uint32_t s, const float* g) {
    asm volatile("cp.async.cg.shared.global [%0], [%1], 16;\n" :: "r"(s), "l"(g));
}
#define CP_COMMIT() asm volatile("cp.async.commit_group;\n" ::: "memory")
#define CP_WAIT(N)  asm volatile("cp.async.wait_group %0;\n" :: "n"(N) : "memory")

// ---------- Kernel 1: xg = x @ Wx + b, relayout to [t][blk][row][g*8+j] ----------
// (proven R4 version, unchanged)
__global__ void __launch_bounds__(128) xg_kernel(const float* __restrict__ x,
                                                 const float* __restrict__ Wx,
                                                 const float* __restrict__ bias) {
    __shared__ float As[64][33];
    __shared__ float Bs[32][65];

    const int tid  = threadIdx.x;
    const int w    = tid >> 5;
    const int lane = tid & 31;
    const int gid  = lane >> 2;
    const int tig  = lane & 3;
    const int wm   = w >> 1;
    const int wn   = w & 1;

    const int m0 = blockIdx.y * 64;
    const int c0 = blockIdx.x * 64;

    float acc[2][4][4];
#pragma unroll
    for (int mi = 0; mi < 2; mi++)
#pragma unroll
        for (int ni = 0; ni < 4; ni++)
#pragma unroll
            for (int j = 0; j < 4; j++) acc[mi][ni][j] = 0.f;

    for (int kc = 0; kc < DD; kc += 32) {
#pragma unroll
        for (int i = 0; i < 4; i++) {
            int id  = tid + i * 128;
            int row = id >> 3;
            int k4  = (id & 7) * 4;
            float4 v = *reinterpret_cast<const float4*>(x + (size_t)(m0 + row) * DD + kc + k4);
            As[row][k4 + 0] = tfbits(v.x);
            As[row][k4 + 1] = tfbits(v.y);
            As[row][k4 + 2] = tfbits(v.z);
            As[row][k4 + 3] = tfbits(v.w);
        }
#pragma unroll
        for (int i = 0; i < 4; i++) {
            int id = tid + i * 128;
            int k  = id >> 4;
            int n4 = (id & 15) * 4;
            float4 v = *reinterpret_cast<const float4*>(Wx + (size_t)(kc + k) * G4 + c0 + n4);
            Bs[k][n4 + 0] = tfbits(v.x);
            Bs[k][n4 + 1] = tfbits(v.y);
            Bs[k][n4 + 2] = tfbits(v.z);
            Bs[k][n4 + 3] = tfbits(v.w);
        }
        __syncthreads();

#pragma unroll
        for (int q = 0; q < 4; q++) {
            const int kk = q * 8 + tig;
            unsigned a[2][4];
#pragma unroll
            for (int mi = 0; mi < 2; mi++) {
                int r0 = wm * 32 + mi * 16 + gid;
                a[mi][0] = fu(As[r0][kk]);
                a[mi][1] = fu(As[r0 + 8][kk]);
                a[mi][2] = fu(As[r0][kk + 4]);
                a[mi][3] = fu(As[r0 + 8][kk + 4]);
            }
#pragma unroll
            for (int ni = 0; ni < 4; ni++) {
                int cb = wn * 32 + ni * 8 + gid;
                unsigned b0 = fu(Bs[kk][cb]);
                unsigned b1 = fu(Bs[kk + 4][cb]);
#pragma unroll
                for (int mi = 0; mi < 2; mi++) mma_tf32(acc[mi][ni], a[mi], b0, b1);
            }
        }
        __syncthreads();
    }

#pragma unroll
    for (int mi = 0; mi < 2; mi++) {
#pragma unroll
        for (int ni = 0; ni < 4; ni++) {
#pragma unroll
            for (int j = 0; j < 4; j++) {
                int m   = m0 + wm * 32 + mi * 16 + gid + ((j >= 2) ? 8 : 0);
                int col = c0 + wn * 32 + ni * 8 + tig * 2 + (j & 1);
                float v = acc[mi][ni][j] + bias[col];
                int b   = m >> 9;        // batch
                int t   = m & (TT - 1);  // time
                int g   = col >> 10;
                int u   = col & (UU - 1);
                int blk = u >> 3;
                int jj  = u & 7;
                g_xg[(((size_t)t * NBLK + blk) * BB + b) * 32 + g * 8 + jj] = v;
            }
        }
    }
}

// ---------- init: h0 -> g_h buffer0 with tf32 rounding ----------
__global__ void init_h(const float* __restrict__ h0) {
    int i = blockIdx.x * blockDim.x + threadIdx.x;
    if (i < BB * UU) g_h[i] = tfbits(h0[i]);
}

// ---------- persistent LSTM kernel ----------
// 128 blocks x 256 threads, 1 block/SM. Block owns u-cols u0..u0+7, all 4 gates.
// Wh slice SMEM-resident (pre-swizzled tf32 B-fragments). c in registers.
// h ping-pong via L2; 3-deep cp.async; STAGGERED per-chunk producer flags.
__global__ void __launch_bounds__(NTHR, 1) lstm_persistent(const float* __restrict__ Wh,
                                                           const float* __restrict__ c0,
                                                           float* __restrict__ out) {
    extern __shared__ float smem[];
    float* FB = smem;                 // 32768 f: B-fragments
    float* HS = FB + 32768;           // 4 * 64*68 f: h staging
    float* GM = HS + 4 * 64 * 68;     // 64*33 f: gate exchange

    const int tid  = threadIdx.x;
    const int w    = tid >> 5;
    const int lane = tid & 31;
    const int gid  = lane >> 2;
    const int tig  = lane & 3;
    const int wm   = w & 3;
    const int wn   = w >> 2;
    const int blk  = blockIdx.x;
    const int u0   = blk * 8;

    // one-time: Wh fragments (tf32, pre-swizzled)
    for (int idx = tid; idx < 32768; idx += NTHR) {
        int e     = idx & 7;
        int ln    = (idx >> 3) & 31;
        int tile  = (idx >> 8) & 3;
        int kcc32 = idx >> 10;
        int q     = e >> 1;
        int pair  = e & 1;
        int lgid  = ln >> 2;
        int ltig  = ln & 3;
        int k     = kcc32 * 32 + q * 8 + ltig + pair * 4;
        FB[idx] = tfbits(Wh[(size_t)k * G4 + tile * UU + u0 + lgid]);
    }

    float creg[2];
#pragma unroll
    for (int i = 0; i < 2; i++) {
        int e = tid + i * NTHR;
        int row = e >> 3, j = e & 7;
        creg[i] = c0[(size_t)row * UU + u0 + j];
    }
    __syncthreads();

    const float4* FB4 = reinterpret_cast<const float4*>(FB);
    const uint32_t hs_base = (uint32_t)__cvta_generic_to_shared(HS);
    const int r0 = wm * 16 + gid;
    const int t0i = wn * 2, t1i = wn * 2 + 1;

    volatile unsigned* vflag = (volatile unsigned*)g_flag;

    for (int t = 0; t < TT; t++) {
        const float* h_in = g_h + (size_t)(t & 1) * BB * UU;
        float* h_out      = g_h + (size_t)((t + 1) & 1) * BB * UU;
        const float* xgt  = g_xg + ((size_t)t * NBLK + blk) * (BB * 32);

        // ---- wait only for producers of chunks 0..2 (blocks 0..23) ----
        if (t > 0 && tid < 24) {
            while (vflag[tid] < (unsigned)t) { }
            __threadfence();   // order subsequent h reads after flag observation
        }
        __syncthreads();

        float acc0[4] = {0.f, 0.f, 0.f, 0.f};
        float acc1[4] = {0.f, 0.f, 0.f, 0.f};

        // prologue: chunks 0..2 (3 groups in flight)
#pragma unroll
        for (int p = 0; p <= 2; p++) {
#pragma unroll
            for (int i = 0; i < 4; i++) {
                int id = tid + i * NTHR;
                int row = id >> 4, kq = id & 15;
                cp_async16(hs_base + (uint32_t)((p * 4352 + row * 68 + kq * 4) * 4),
                           h_in + (size_t)row * UU + p * 64 + kq * 4);
            }
            CP_COMMIT();
        }

        // xg slab prefetch into registers (plain LDG; consumed only in epilogue,
        // so its DRAM latency hides under the whole k-loop)
        float xr[8];
#pragma unroll
        for (int i = 0; i < 2; i++) {
            int e = tid + i * NTHR;
            int row = e >> 3, j = e & 7;
#pragma unroll
            for (int g = 0; g < 4; g++)
                xr[i * 4 + g] = __ldg(xgt + row * 32 + g * 8 + j);
        }

        for (int kcc = 0; kcc < 16; kcc++) {
            // staggered wait: chunk kcc+3's 8 producer flags, overlapped with CP_WAIT
            if (t > 0 && kcc + 3 < 16 && tid < 8) {
                const int pb = 8 * (kcc + 3) + tid;
                while (vflag[pb] < (unsigned)t) { }
                __threadfence();
            }
            CP_WAIT(2);
            __syncthreads();   // pollers done + staged data visible + buffer free

            if (kcc + 3 < 16) {
                int c = kcc + 3;
                int buf = c & 3;
#pragma unroll
                for (int i = 0; i < 4; i++) {
                    int id = tid + i * NTHR;
                    int row = id >> 4, kq = id & 15;
                    cp_async16(hs_base + (uint32_t)((buf * 4352 + row * 68 + kq * 4) * 4),
                               h_in + (size_t)row * UU + c * 64 + kq * 4);
                }
            }
            CP_COMMIT();       // empty group at tail keeps CP_WAIT(2) uniform

            const float* hb = HS + (kcc & 3) * 4352;
#pragma unroll
            for (int sub = 0; sub < 2; sub++) {
                const int kcc32 = kcc * 2 + sub;
                float4 bA0 = FB4[((kcc32 * 4 + t0i) * 32 + lane) * 2 + 0];
                float4 bA1 = FB4[((kcc32 * 4 + t0i) * 32 + lane) * 2 + 1];
                float4 bB0 = FB4[((kcc32 * 4 + t1i) * 32 + lane) * 2 + 0];
                float4 bB1 = FB4[((kcc32 * 4 + t1i) * 32 + lane) * 2 + 1];
#pragma unroll
                for (int q = 0; q < 4; q++) {
                    const int kk = sub * 32 + q * 8 + tig;
                    unsigned a[4];
                    a[0] = fu(hb[r0 * 68 + kk]);
                    a[1] = fu(hb[(r0 + 8) * 68 + kk]);
                    a[2] = fu(hb[r0 * 68 + kk + 4]);
                    a[3] = fu(hb[(r0 + 8) * 68 + kk + 4]);
                    unsigned b0a, b1a, b0b, b1b;
                    if (q == 0)      { b0a = fu(bA0.x); b1a = fu(bA0.y); b0b = fu(bB0.x); b1b = fu(bB0.y); }
                    else if (q == 1) { b0a = fu(bA0.z); b1a = fu(bA0.w); b0b = fu(bB0.z); b1b = fu(bB0.w); }
                    else if (q == 2) { b0a = fu(bA1.x); b1a = fu(bA1.y); b0b = fu(bB1.x); b1b = fu(bB1.y); }
                    else             { b0a = fu(bA1.z); b1a = fu(bA1.w); b0b = fu(bB1.z); b1b = fu(bB1.w); }
                    mma_tf32(acc0, a, b0a, b1a);
                    mma_tf32(acc1, a, b0b, b1b);
                }
            }
        }
        __syncthreads();  // all compute done before GM writes

        // gate exchange
#pragma unroll
        for (int j = 0; j < 4; j++) {
            int row = wm * 16 + gid + ((j >> 1) ? 8 : 0);
            GM[row * 33 + t0i * 8 + tig * 2 + (j & 1)] = acc0[j];
            GM[row * 33 + t1i * 8 + tig * 2 + (j & 1)] = acc1[j];
        }
        __syncthreads();

        // epilogue: gates + c/h update (xg from registers)
#pragma unroll
        for (int i = 0; i < 2; i++) {
            int e = tid + i * NTHR;
            int row = e >> 3, j = e & 7;
            float zi = GM[row * 33 + 0 * 8 + j] + xr[i * 4 + 0];
            float zf = GM[row * 33 + 1 * 8 + j] + xr[i * 4 + 1];
            float zg = GM[row * 33 + 2 * 8 + j] + xr[i * 4 + 2];
            float zo = GM[row * 33 + 3 * 8 + j] + xr[i * 4 + 3];

            float ig = fsig(zi);
            float fg = fsig(zf);
            float gg = ftanh(zg);
            float og = fsig(zo);

            creg[i] = fg * creg[i] + ig * gg;
            float hv = og * ftanh(creg[i]);
            if (t == TT - 1) out[(size_t)row * UU + u0 + j] = hv;
            else             h_out[(size_t)row * UU + u0 + j] = tfbits(hv);
        }

        // publish completion (proven R4 protocol)
        __syncthreads();
        if (t + 1 < TT && tid == 0) {
            __threadfence();
            atomicExch(&g_flag[blk], (unsigned)(t + 1));
        }
    }
}

// ---------- launch ----------
extern "C" void kernel_launch(void* const* d_in, const int* in_sizes, int n_in,
                              void* d_out, int out_size) {
    const float *x = nullptr, *h0 = nullptr, *c0 = nullptr;
    const float *Wx = nullptr, *Wh = nullptr, *bias = nullptr;
    for (int i = 0; i < n_in; i++) {
        const int s = in_sizes[i];
        const float* p = (const float*)d_in[i];
        if      (s == BB * TT * DD) x = p;
        else if (s == DD * G4)      Wx = p;
        else if (s == UU * G4)      Wh = p;
        else if (s == G4)           bias = p;
        else if (s == BB * UU)      { if (!h0) h0 = p; else c0 = p; }
    }

    const int LSTM_SMEM = (32768 + 4 * 64 * 68 + 64 * 33) * 4;

    static bool attr_set = false;
    if (!attr_set) {
        cudaFuncSetAttribute(lstm_persistent,
                             cudaFuncAttributeMaxDynamicSharedMemorySize, LSTM_SMEM);
        attr_set = true;
    }

    void* flg = nullptr;
    cudaGetSymbolAddress(&flg, g_flag);
    cudaMemsetAsync(flg, 0, NBLK * sizeof(unsigned), 0);

    init_h<<<(BB * UU + 255) / 256, 256>>>(h0);
    xg_kernel<<<dim3(G4 / 64, (BB * TT) / 64), 128>>>(x, Wx, bias);

    lstm_persistent<<<NBLK, NTHR, LSTM_SMEM>>>(Wh, c0, (float*)d_out);
}

// round 8
// speedup vs baseline: 1.6803x; 1.5180x over previous
#include <cuda_runtime.h>
#include <cstdint>
#include <math.h>

#define BB 64
#define TT 512
#define DD 512
#define UU 1024
#define G4 4096   // 4*UU
#define NBLK 128
#define NTHR 256

// Scratch (allocation-free rule: __device__ globals)
__device__ float g_xg[(size_t)TT * NBLK * BB * 32];  // [t][blk][row][g*8+j] = 512MB
// h ping-pong in FRAGMENT layout:
// gidx(u,row) = (((u>>6)*2 + ((u>>5)&1))*64 + row)*32 + (u&3)*8 + ((u&31)>>2)
__device__ float g_h[2 * BB * UU];
__device__ unsigned g_flag[NBLK];                    // per-block completed-step count

// ---------- helpers ----------
__device__ __forceinline__ unsigned f2tf(float x) {
    unsigned r;
    asm volatile("cvt.rna.tf32.f32 %0, %1;" : "=r"(r) : "f"(x));
    return r;
}
__device__ __forceinline__ float tfbits(float x) { return __uint_as_float(f2tf(x)); }
__device__ __forceinline__ unsigned fu(float x) { return __float_as_uint(x); }

__device__ __forceinline__ void mma_tf32(float d[4], const unsigned a[4], unsigned b0, unsigned b1) {
    asm volatile(
        "mma.sync.aligned.m16n8k8.row.col.f32.tf32.tf32.f32 "
        "{%0,%1,%2,%3}, {%4,%5,%6,%7}, {%8,%9}, {%0,%1,%2,%3};"
        : "+f"(d[0]), "+f"(d[1]), "+f"(d[2]), "+f"(d[3])
        : "r"(a[0]), "r"(a[1]), "r"(a[2]), "r"(a[3]), "r"(b0), "r"(b1));
}

__device__ __forceinline__ float fsig(float z) { return 1.f / (1.f + __expf(-z)); }
__device__ __forceinline__ float ftanh(float z) { return 2.f / (1.f + __expf(-2.f * z)) - 1.f; }

__device__ __forceinline__ void cp_async16(uint32_t s, const float* g) {
    asm volatile("cp.async.cg.shared.global [%0], [%1], 16;\n" :: "r"(s), "l"(g));
}
#define CP_COMMIT() asm volatile("cp.async.commit_group;\n" ::: "memory")
#define CP_WAIT(N)  asm volatile("cp.async.wait_group %0;\n" :: "n"(N) : "memory")

// fragment-layout index for h: u in [0,1024), row in [0,64)
__device__ __forceinline__ int h_gidx(int u, int row) {
    int chunk = u >> 6;
    int sub   = (u >> 5) & 1;
    int tig   = u & 3;
    int m     = (u & 31) >> 2;
    return (((chunk * 2 + sub) * 64) + row) * 32 + tig * 8 + m;
}

// ---------- Kernel 1: xg = x @ Wx + b, relayout to [t][blk][row][g*8+j] ----------
// (proven R4 version, unchanged)
__global__ void __launch_bounds__(128) xg_kernel(const float* __restrict__ x,
                                                 const float* __restrict__ Wx,
                                                 const float* __restrict__ bias) {
    __shared__ float As[64][33];
    __shared__ float Bs[32][65];

    const int tid  = threadIdx.x;
    const int w    = tid >> 5;
    const int lane = tid & 31;
    const int gid  = lane >> 2;
    const int tig  = lane & 3;
    const int wm   = w >> 1;
    const int wn   = w & 1;

    const int m0 = blockIdx.y * 64;
    const int c0 = blockIdx.x * 64;

    float acc[2][4][4];
#pragma unroll
    for (int mi = 0; mi < 2; mi++)
#pragma unroll
        for (int ni = 0; ni < 4; ni++)
#pragma unroll
            for (int j = 0; j < 4; j++) acc[mi][ni][j] = 0.f;

    for (int kc = 0; kc < DD; kc += 32) {
#pragma unroll
        for (int i = 0; i < 4; i++) {
            int id  = tid + i * 128;
            int row = id >> 3;
            int k4  = (id & 7) * 4;
            float4 v = *reinterpret_cast<const float4*>(x + (size_t)(m0 + row) * DD + kc + k4);
            As[row][k4 + 0] = tfbits(v.x);
            As[row][k4 + 1] = tfbits(v.y);
            As[row][k4 + 2] = tfbits(v.z);
            As[row][k4 + 3] = tfbits(v.w);
        }
#pragma unroll
        for (int i = 0; i < 4; i++) {
            int id = tid + i * 128;
            int k  = id >> 4;
            int n4 = (id & 15) * 4;
            float4 v = *reinterpret_cast<const float4*>(Wx + (size_t)(kc + k) * G4 + c0 + n4);
            Bs[k][n4 + 0] = tfbits(v.x);
            Bs[k][n4 + 1] = tfbits(v.y);
            Bs[k][n4 + 2] = tfbits(v.z);
            Bs[k][n4 + 3] = tfbits(v.w);
        }
        __syncthreads();

#pragma unroll
        for (int q = 0; q < 4; q++) {
            const int kk = q * 8 + tig;
            unsigned a[2][4];
#pragma unroll
            for (int mi = 0; mi < 2; mi++) {
                int r0 = wm * 32 + mi * 16 + gid;
                a[mi][0] = fu(As[r0][kk]);
                a[mi][1] = fu(As[r0 + 8][kk]);
                a[mi][2] = fu(As[r0][kk + 4]);
                a[mi][3] = fu(As[r0 + 8][kk + 4]);
            }
#pragma unroll
            for (int ni = 0; ni < 4; ni++) {
                int cb = wn * 32 + ni * 8 + gid;
                unsigned b0 = fu(Bs[kk][cb]);
                unsigned b1 = fu(Bs[kk + 4][cb]);
#pragma unroll
                for (int mi = 0; mi < 2; mi++) mma_tf32(acc[mi][ni], a[mi], b0, b1);
            }
        }
        __syncthreads();
    }

#pragma unroll
    for (int mi = 0; mi < 2; mi++) {
#pragma unroll
        for (int ni = 0; ni < 4; ni++) {
#pragma unroll
            for (int j = 0; j < 4; j++) {
                int m   = m0 + wm * 32 + mi * 16 + gid + ((j >= 2) ? 8 : 0);
                int col = c0 + wn * 32 + ni * 8 + tig * 2 + (j & 1);
                float v = acc[mi][ni][j] + bias[col];
                int b   = m >> 9;        // batch
                int t   = m & (TT - 1);  // time
                int g   = col >> 10;
                int u   = col & (UU - 1);
                int blk = u >> 3;
                int jj  = u & 7;
                g_xg[(((size_t)t * NBLK + blk) * BB + b) * 32 + g * 8 + jj] = v;
            }
        }
    }
}

// ---------- init: h0 -> g_h buffer0 (fragment layout) with tf32 rounding ----------
__global__ void init_h(const float* __restrict__ h0) {
    int i = blockIdx.x * blockDim.x + threadIdx.x;
    if (i < BB * UU) {
        int row = i >> 10;
        int u   = i & (UU - 1);
        g_h[h_gidx(u, row)] = tfbits(h0[i]);
    }
}

// ---------- persistent LSTM kernel ----------
// 128 blocks x 256 threads, 1 block/SM. Block owns u-cols u0..u0+7, all 4 gates.
// Wh slice SMEM-resident (pre-swizzled tf32 B-fragments). c in registers.
// h ping-pong via L2 in FRAGMENT layout -> A-fragments = 8 LDS.128/thread/chunk.
#define HS_STRIDE 36            // floats per staged 32-float row (+4 pad)
#define HS_BUF    (128 * HS_STRIDE)  // 4608 floats per chunk buffer
__global__ void __launch_bounds__(NTHR, 1) lstm_persistent(const float* __restrict__ Wh,
                                                           const float* __restrict__ c0,
                                                           float* __restrict__ out) {
    extern __shared__ float smem[];
    float* FB  = smem;                  // 32768 f: B-fragments
    float* HS  = FB + 32768;            // 4 * 4608 f: h staging (fragment layout)
    float* XGS = HS + 4 * HS_BUF;       // 2048 f: xg slab
    float* GM  = XGS + 2048;            // 64*33 f: gate exchange

    const int tid  = threadIdx.x;
    const int w    = tid >> 5;
    const int lane = tid & 31;
    const int gid  = lane >> 2;
    const int tig  = lane & 3;
    const int wm   = w & 3;
    const int wn   = w >> 2;
    const int blk  = blockIdx.x;
    const int u0   = blk * 8;

    // one-time: Wh fragments (tf32, pre-swizzled)
    for (int idx = tid; idx < 32768; idx += NTHR) {
        int e     = idx & 7;
        int ln    = (idx >> 3) & 31;
        int tile  = (idx >> 8) & 3;
        int kcc32 = idx >> 10;
        int q     = e >> 1;
        int pair  = e & 1;
        int lgid  = ln >> 2;
        int ltig  = ln & 3;
        int k     = kcc32 * 32 + q * 8 + ltig + pair * 4;
        FB[idx] = tfbits(Wh[(size_t)k * G4 + tile * UU + u0 + lgid]);
    }

    float creg[2];
#pragma unroll
    for (int i = 0; i < 2; i++) {
        int e = tid + i * NTHR;
        int row = e >> 3, j = e & 7;
        creg[i] = c0[(size_t)row * UU + u0 + j];
    }
    __syncthreads();

    const float4* FB4 = reinterpret_cast<const float4*>(FB);
    const uint32_t hs_base  = (uint32_t)__cvta_generic_to_shared(HS);
    const uint32_t xgs_base = (uint32_t)__cvta_generic_to_shared(XGS);
    const int r0 = wm * 16 + gid;
    const int t0i = wn * 2, t1i = wn * 2 + 1;

    // epilogue write constants (fragment layout)
    const int ch2  = (blk >> 3) * 2 + ((blk >> 2) & 1);  // (chunk*2 + sub)
    volatile unsigned* vflag = (volatile unsigned*)g_flag;

    for (int t = 0; t < TT; t++) {
        const float* h_in = g_h + (size_t)(t & 1) * BB * UU;
        float* h_out      = g_h + (size_t)((t + 1) & 1) * BB * UU;
        const float* xgt  = g_xg + ((size_t)t * NBLK + blk) * (BB * 32);

        // ---- wait for ALL producers of h_t (single wide poll, proven R4) ----
        if (t > 0 && tid < NBLK) {
            while (vflag[tid] < (unsigned)t) { }
            __threadfence();
        }
        __syncthreads();

        float acc0[4] = {0.f, 0.f, 0.f, 0.f};
        float acc1[4] = {0.f, 0.f, 0.f, 0.f};

        // prologue: xg slab + chunks 0..2 (3 groups in flight), R4 bundling
        {
#pragma unroll
            for (int i = 0; i < 2; i++) {
                int id = tid + i * NTHR;          // 0..511 float4s
                cp_async16(xgs_base + (uint32_t)(id * 16), xgt + id * 4);
            }
#pragma unroll
            for (int i = 0; i < 4; i++) {
                int id = tid + i * NTHR;          // 0..1023
                int s64 = id >> 3, seg = id & 7;
                cp_async16(hs_base + (uint32_t)((s64 * HS_STRIDE + seg * 4) * 4),
                           h_in + 0 * 4096 + s64 * 32 + seg * 4);
            }
            CP_COMMIT();
#pragma unroll
            for (int p = 1; p <= 2; p++) {
#pragma unroll
                for (int i = 0; i < 4; i++) {
                    int id = tid + i * NTHR;
                    int s64 = id >> 3, seg = id & 7;
                    cp_async16(hs_base + (uint32_t)((p * HS_BUF + s64 * HS_STRIDE + seg * 4) * 4),
                               h_in + (size_t)p * 4096 + s64 * 32 + seg * 4);
                }
                CP_COMMIT();
            }
        }

        for (int kcc = 0; kcc < 16; kcc++) {
            CP_WAIT(2);
            __syncthreads();

            if (kcc + 3 < 16) {
                int c = kcc + 3;
                int buf = c & 3;
#pragma unroll
                for (int i = 0; i < 4; i++) {
                    int id = tid + i * NTHR;
                    int s64 = id >> 3, seg = id & 7;
                    cp_async16(hs_base + (uint32_t)((buf * HS_BUF + s64 * HS_STRIDE + seg * 4) * 4),
                               h_in + (size_t)c * 4096 + s64 * 32 + seg * 4);
                }
            }
            CP_COMMIT();       // empty group at tail keeps CP_WAIT(2) uniform

            const float* hb = HS + (kcc & 3) * HS_BUF;
#pragma unroll
            for (int sub = 0; sub < 2; sub++) {
                const int kcc32 = kcc * 2 + sub;
                // A fragments: 4 LDS.128 (rows r0, r0+8; m 0-3 and 4-7)
                const float* pa = hb + (sub * 64 + r0) * HS_STRIDE + tig * 8;
                const float* pb = hb + (sub * 64 + r0 + 8) * HS_STRIDE + tig * 8;
                float4 fA0 = *reinterpret_cast<const float4*>(pa);
                float4 fA1 = *reinterpret_cast<const float4*>(pa + 4);
                float4 fB0 = *reinterpret_cast<const float4*>(pb);
                float4 fB1 = *reinterpret_cast<const float4*>(pb + 4);
                // B fragments: 4 LDS.128 (two tiles)
                float4 bA0 = FB4[((kcc32 * 4 + t0i) * 32 + lane) * 2 + 0];
                float4 bA1 = FB4[((kcc32 * 4 + t0i) * 32 + lane) * 2 + 1];
                float4 bB0 = FB4[((kcc32 * 4 + t1i) * 32 + lane) * 2 + 0];
                float4 bB1 = FB4[((kcc32 * 4 + t1i) * 32 + lane) * 2 + 1];
#pragma unroll
                for (int q = 0; q < 4; q++) {
                    unsigned a[4];
                    if (q == 0)      { a[0]=fu(fA0.x); a[1]=fu(fB0.x); a[2]=fu(fA0.y); a[3]=fu(fB0.y); }
                    else if (q == 1) { a[0]=fu(fA0.z); a[1]=fu(fB0.z); a[2]=fu(fA0.w); a[3]=fu(fB0.w); }
                    else if (q == 2) { a[0]=fu(fA1.x); a[1]=fu(fB1.x); a[2]=fu(fA1.y); a[3]=fu(fB1.y); }
                    else             { a[0]=fu(fA1.z); a[1]=fu(fB1.z); a[2]=fu(fA1.w); a[3]=fu(fB1.w); }
                    unsigned b0a, b1a, b0b, b1b;
                    if (q == 0)      { b0a = fu(bA0.x); b1a = fu(bA0.y); b0b = fu(bB0.x); b1b = fu(bB0.y); }
                    else if (q == 1) { b0a = fu(bA0.z); b1a = fu(bA0.w); b0b = fu(bB0.z); b1b = fu(bB0.w); }
                    else if (q == 2) { b0a = fu(bA1.x); b1a = fu(bA1.y); b0b = fu(bB1.x); b1b = fu(bB1.y); }
                    else             { b0a = fu(bA1.z); b1a = fu(bA1.w); b0b = fu(bB1.z); b1b = fu(bB1.w); }
                    mma_tf32(acc0, a, b0a, b1a);
                    mma_tf32(acc1, a, b0b, b1b);
                }
            }
        }
        __syncthreads();

        // gate exchange
#pragma unroll
        for (int j = 0; j < 4; j++) {
            int row = wm * 16 + gid + ((j >> 1) ? 8 : 0);
            GM[row * 33 + t0i * 8 + tig * 2 + (j & 1)] = acc0[j];
            GM[row * 33 + t1i * 8 + tig * 2 + (j & 1)] = acc1[j];
        }
        __syncthreads();

        // epilogue: gates + c/h update (xg from SMEM); h written in fragment layout
#pragma unroll
        for (int i = 0; i < 2; i++) {
            int e = tid + i * NTHR;
            int row = e >> 3, j = e & 7;
            float zi = GM[row * 33 + 0 * 8 + j] + XGS[row * 32 + 0 * 8 + j];
            float zf = GM[row * 33 + 1 * 8 + j] + XGS[row * 32 + 1 * 8 + j];
            float zg = GM[row * 33 + 2 * 8 + j] + XGS[row * 32 + 2 * 8 + j];
            float zo = GM[row * 33 + 3 * 8 + j] + XGS[row * 32 + 3 * 8 + j];

            float ig = fsig(zi);
            float fg = fsig(zf);
            float gg = ftanh(zg);
            float og = fsig(zo);

            creg[i] = fg * creg[i] + ig * gg;
            float hv = og * ftanh(creg[i]);
            if (t == TT - 1) {
                out[(size_t)row * UU + u0 + j] = hv;
            } else {
                int mv   = (blk & 3) * 2 + (j >> 2);
                int tigv = j & 3;
                h_out[(ch2 * 64 + row) * 32 + tigv * 8 + mv] = tfbits(hv);
            }
        }

        // publish completion (proven R4 protocol)
        __syncthreads();
        if (t + 1 < TT && tid == 0) {
            __threadfence();
            atomicExch(&g_flag[blk], (unsigned)(t + 1));
        }
    }
}

// ---------- launch ----------
extern "C" void kernel_launch(void* const* d_in, const int* in_sizes, int n_in,
                              void* d_out, int out_size) {
    const float *x = nullptr, *h0 = nullptr, *c0 = nullptr;
    const float *Wx = nullptr, *Wh = nullptr, *bias = nullptr;
    for (int i = 0; i < n_in; i++) {
        const int s = in_sizes[i];
        const float* p = (const float*)d_in[i];
        if      (s == BB * TT * DD) x = p;
        else if (s == DD * G4)      Wx = p;
        else if (s == UU * G4)      Wh = p;
        else if (s == G4)           bias = p;
        else if (s == BB * UU)      { if (!h0) h0 = p; else c0 = p; }
    }

    const int LSTM_SMEM = (32768 + 4 * HS_BUF + 2048 + 64 * 33) * 4;

    static bool attr_set = false;
    if (!attr_set) {
        cudaFuncSetAttribute(lstm_persistent,
                             cudaFuncAttributeMaxDynamicSharedMemorySize, LSTM_SMEM);
        attr_set = true;
    }

    void* flg = nullptr;
    cudaGetSymbolAddress(&flg, g_flag);
    cudaMemsetAsync(flg, 0, NBLK * sizeof(unsigned), 0);

    init_h<<<(BB * UU + 255) / 256, 256>>>(h0);
    xg_kernel<<<dim3(G4 / 64, (BB * TT) / 64), 128>>>(x, Wx, bias);

    lstm_persistent<<<NBLK, NTHR, LSTM_SMEM>>>(Wh, c0, (float*)d_out);
}

// round 9
// speedup vs baseline: 1.9675x; 1.1709x over previous
#include <cuda_runtime.h>
#include <cstdint>
#include <math.h>

#define BB 64
#define TT 512
#define DD 512
#define UU 1024
#define G4 4096   // 4*UU
#define NBLK 128
#define NTHR 256

// Scratch (allocation-free rule: __device__ globals)
__device__ float g_xg[(size_t)TT * NBLK * BB * 32];  // [t][blk][row][g*8+j] = 512MB
__device__ float g_Wxtf[(size_t)DD * G4];            // tf32-rounded Wx (8MB)
// h ping-pong in FRAGMENT layout:
// gidx(u,row) = (((u>>6)*2 + ((u>>5)&1))*64 + row)*32 + (u&3)*8 + ((u&31)>>2)
__device__ float g_h[2 * BB * UU];
__device__ unsigned g_flag[NBLK];                    // per-block completed-step count

// ---------- helpers ----------
__device__ __forceinline__ unsigned f2tf(float x) {
    unsigned r;
    asm volatile("cvt.rna.tf32.f32 %0, %1;" : "=r"(r) : "f"(x));
    return r;
}
__device__ __forceinline__ float tfbits(float x) { return __uint_as_float(f2tf(x)); }
__device__ __forceinline__ unsigned fu(float x) { return __float_as_uint(x); }
__device__ __forceinline__ unsigned futf(float x) { return f2tf(x); }

__device__ __forceinline__ void mma_tf32(float d[4], const unsigned a[4], unsigned b0, unsigned b1) {
    asm volatile(
        "mma.sync.aligned.m16n8k8.row.col.f32.tf32.tf32.f32 "
        "{%0,%1,%2,%3}, {%4,%5,%6,%7}, {%8,%9}, {%0,%1,%2,%3};"
        : "+f"(d[0]), "+f"(d[1]), "+f"(d[2]), "+f"(d[3])
        : "r"(a[0]), "r"(a[1]), "r"(a[2]), "r"(a[3]), "r"(b0), "r"(b1));
}

__device__ __forceinline__ float fsig(float z) { return 1.f / (1.f + __expf(-z)); }
__device__ __forceinline__ float ftanh(float z) { return 2.f / (1.f + __expf(-2.f * z)) - 1.f; }

__device__ __forceinline__ void cp_async16(uint32_t s, const float* g) {
    asm volatile("cp.async.cg.shared.global [%0], [%1], 16;\n" :: "r"(s), "l"(g));
}
#define CP_COMMIT() asm volatile("cp.async.commit_group;\n" ::: "memory")
#define CP_WAIT(N)  asm volatile("cp.async.wait_group %0;\n" :: "n"(N) : "memory")

// fragment-layout index for h: u in [0,1024), row in [0,64)
__device__ __forceinline__ int h_gidx(int u, int row) {
    int chunk = u >> 6;
    int sub   = (u >> 5) & 1;
    int tig   = u & 3;
    int m     = (u & 31) >> 2;
    return (((chunk * 2 + sub) * 64) + row) * 32 + tig * 8 + m;
}

// ---------- Kernel 1: prep — tf32-round Wx; h0 -> g_h (fragment layout); clear flags ----------
__global__ void __launch_bounds__(256) prep(const float* __restrict__ h0,
                                            const float* __restrict__ Wx) {
    int idx = blockIdx.x * 256 + threadIdx.x;
    if (idx < DD * G4) g_Wxtf[idx] = tfbits(Wx[idx]);
    if (idx < BB * UU) {
        int row = idx >> 10;
        int u   = idx & (UU - 1);
        g_h[h_gidx(u, row)] = tfbits(h0[idx]);
    }
    if (idx < NBLK) g_flag[idx] = 0;
}

// ---------- Kernel 2: xg = x @ Wx + b (pipelined, 4-stage cp.async) ----------
// BM=128, BN=64, BK=32, 256 threads (8 warps: wm=w>>1 in 0..3, wn=w&1).
// Output relayout [t][blk][row][g*8+j] (identical to R4/R8).
#define XA_ST (128 * 36)   // 4608 floats per A stage
#define XB_ST (32 * 68)    // 2176 floats per B stage
__global__ void __launch_bounds__(256, 2) xg_kernel(const float* __restrict__ x,
                                                    const float* __restrict__ bias) {
    extern __shared__ float sm[];
    float* As = sm;               // 4 stages
    float* Bs = sm + 4 * XA_ST;   // 4 stages

    const int tid  = threadIdx.x;
    const int w    = tid >> 5;
    const int lane = tid & 31;
    const int gid  = lane >> 2;
    const int tig  = lane & 3;
    const int wm   = w >> 1;      // 0..3 : rows wm*32
    const int wn   = w & 1;       // 0..1 : cols wn*32

    const int m0 = blockIdx.y * 128;
    const int c0 = blockIdx.x * 64;

    const uint32_t as_base = (uint32_t)__cvta_generic_to_shared(As);
    const uint32_t bs_base = (uint32_t)__cvta_generic_to_shared(Bs);

    float acc[2][4][4];
#pragma unroll
    for (int mi = 0; mi < 2; mi++)
#pragma unroll
        for (int ni = 0; ni < 4; ni++)
#pragma unroll
            for (int j = 0; j < 4; j++) acc[mi][ni][j] = 0.f;

    auto issue = [&](int kc, int s) {
#pragma unroll
        for (int i = 0; i < 4; i++) {
            int id  = tid + i * 256;            // 0..1023 float4s
            int row = id >> 3;
            int k4  = (id & 7) * 4;
            cp_async16(as_base + (uint32_t)((s * XA_ST + row * 36 + k4) * 4),
                       x + (size_t)(m0 + row) * DD + kc * 32 + k4);
        }
#pragma unroll
        for (int i = 0; i < 2; i++) {
            int id = tid + i * 256;             // 0..511 float4s
            int k  = id >> 4;
            int n4 = (id & 15) * 4;
            cp_async16(bs_base + (uint32_t)((s * XB_ST + k * 68 + n4) * 4),
                       g_Wxtf + (size_t)(kc * 32 + k) * G4 + c0 + n4);
        }
    };

    issue(0, 0); CP_COMMIT();
    issue(1, 1); CP_COMMIT();
    issue(2, 2); CP_COMMIT();

    for (int kc = 0; kc < 16; kc++) {
        CP_WAIT(2);
        __syncthreads();
        if (kc + 3 < 16) issue(kc + 3, (kc + 3) & 3);
        CP_COMMIT();

        const float* A = As + (kc & 3) * XA_ST;
        const float* B = Bs + (kc & 3) * XB_ST;
#pragma unroll
        for (int q = 0; q < 4; q++) {
            const int kk = q * 8 + tig;
            unsigned a[2][4];
#pragma unroll
            for (int mi = 0; mi < 2; mi++) {
                int r0 = wm * 32 + mi * 16 + gid;
                a[mi][0] = futf(A[r0 * 36 + kk]);          // cvt.rna.tf32 on load
                a[mi][1] = futf(A[(r0 + 8) * 36 + kk]);
                a[mi][2] = futf(A[r0 * 36 + kk + 4]);
                a[mi][3] = futf(A[(r0 + 8) * 36 + kk + 4]);
            }
#pragma unroll
            for (int ni = 0; ni < 4; ni++) {
                int cb = wn * 32 + ni * 8 + gid;
                unsigned b0 = fu(B[kk * 68 + cb]);          // pre-converted
                unsigned b1 = fu(B[(kk + 4) * 68 + cb]);
#pragma unroll
                for (int mi = 0; mi < 2; mi++) mma_tf32(acc[mi][ni], a[mi], b0, b1);
            }
        }
        __syncthreads();
    }

    // epilogue: +bias, scatter to [t][blk][row][g*8+j]
#pragma unroll
    for (int mi = 0; mi < 2; mi++) {
#pragma unroll
        for (int ni = 0; ni < 4; ni++) {
#pragma unroll
            for (int j = 0; j < 4; j++) {
                int m   = m0 + wm * 32 + mi * 16 + gid + ((j >= 2) ? 8 : 0);
                int col = c0 + wn * 32 + ni * 8 + tig * 2 + (j & 1);
                float v = acc[mi][ni][j] + bias[col];
                int b   = m >> 9;        // batch
                int t   = m & (TT - 1);  // time
                int g   = col >> 10;
                int u   = col & (UU - 1);
                int blk = u >> 3;
                int jj  = u & 7;
                g_xg[(((size_t)t * NBLK + blk) * BB + b) * 32 + g * 8 + jj] = v;
            }
        }
    }
}

// ---------- Kernel 3: persistent LSTM (byte-identical to proven R8 version) ----------
#define HS_STRIDE 36            // floats per staged 32-float row (+4 pad)
#define HS_BUF    (128 * HS_STRIDE)  // 4608 floats per chunk buffer
__global__ void __launch_bounds__(NTHR, 1) lstm_persistent(const float* __restrict__ Wh,
                                                           const float* __restrict__ c0,
                                                           float* __restrict__ out) {
    extern __shared__ float smem[];
    float* FB  = smem;                  // 32768 f: B-fragments
    float* HS  = FB + 32768;            // 4 * 4608 f: h staging (fragment layout)
    float* XGS = HS + 4 * HS_BUF;       // 2048 f: xg slab
    float* GM  = XGS + 2048;            // 64*33 f: gate exchange

    const int tid  = threadIdx.x;
    const int w    = tid >> 5;
    const int lane = tid & 31;
    const int gid  = lane >> 2;
    const int tig  = lane & 3;
    const int wm   = w & 3;
    const int wn   = w >> 2;
    const int blk  = blockIdx.x;
    const int u0   = blk * 8;

    // one-time: Wh fragments (tf32, pre-swizzled)
    for (int idx = tid; idx < 32768; idx += NTHR) {
        int e     = idx & 7;
        int ln    = (idx >> 3) & 31;
        int tile  = (idx >> 8) & 3;
        int kcc32 = idx >> 10;
        int q     = e >> 1;
        int pair  = e & 1;
        int lgid  = ln >> 2;
        int ltig  = ln & 3;
        int k     = kcc32 * 32 + q * 8 + ltig + pair * 4;
        FB[idx] = tfbits(Wh[(size_t)k * G4 + tile * UU + u0 + lgid]);
    }

    float creg[2];
#pragma unroll
    for (int i = 0; i < 2; i++) {
        int e = tid + i * NTHR;
        int row = e >> 3, j = e & 7;
        creg[i] = c0[(size_t)row * UU + u0 + j];
    }
    __syncthreads();

    const float4* FB4 = reinterpret_cast<const float4*>(FB);
    const uint32_t hs_base  = (uint32_t)__cvta_generic_to_shared(HS);
    const uint32_t xgs_base = (uint32_t)__cvta_generic_to_shared(XGS);
    const int r0 = wm * 16 + gid;
    const int t0i = wn * 2, t1i = wn * 2 + 1;

    const int ch2  = (blk >> 3) * 2 + ((blk >> 2) & 1);  // (chunk*2 + sub)
    volatile unsigned* vflag = (volatile unsigned*)g_flag;

    for (int t = 0; t < TT; t++) {
        const float* h_in = g_h + (size_t)(t & 1) * BB * UU;
        float* h_out      = g_h + (size_t)((t + 1) & 1) * BB * UU;
        const float* xgt  = g_xg + ((size_t)t * NBLK + blk) * (BB * 32);

        // ---- wait for ALL producers of h_t (single wide poll) ----
        if (t > 0 && tid < NBLK) {
            while (vflag[tid] < (unsigned)t) { }
            __threadfence();
        }
        __syncthreads();

        float acc0[4] = {0.f, 0.f, 0.f, 0.f};
        float acc1[4] = {0.f, 0.f, 0.f, 0.f};

        // prologue: xg slab + chunks 0..2 (3 groups in flight)
        {
#pragma unroll
            for (int i = 0; i < 2; i++) {
                int id = tid + i * NTHR;
                cp_async16(xgs_base + (uint32_t)(id * 16), xgt + id * 4);
            }
#pragma unroll
            for (int i = 0; i < 4; i++) {
                int id = tid + i * NTHR;
                int s64 = id >> 3, seg = id & 7;
                cp_async16(hs_base + (uint32_t)((s64 * HS_STRIDE + seg * 4) * 4),
                           h_in + 0 * 4096 + s64 * 32 + seg * 4);
            }
            CP_COMMIT();
#pragma unroll
            for (int p = 1; p <= 2; p++) {
#pragma unroll
                for (int i = 0; i < 4; i++) {
                    int id = tid + i * NTHR;
                    int s64 = id >> 3, seg = id & 7;
                    cp_async16(hs_base + (uint32_t)((p * HS_BUF + s64 * HS_STRIDE + seg * 4) * 4),
                               h_in + (size_t)p * 4096 + s64 * 32 + seg * 4);
                }
                CP_COMMIT();
            }
        }

        for (int kcc = 0; kcc < 16; kcc++) {
            CP_WAIT(2);
            __syncthreads();

            if (kcc + 3 < 16) {
                int c = kcc + 3;
                int buf = c & 3;
#pragma unroll
                for (int i = 0; i < 4; i++) {
                    int id = tid + i * NTHR;
                    int s64 = id >> 3, seg = id & 7;
                    cp_async16(hs_base + (uint32_t)((buf * HS_BUF + s64 * HS_STRIDE + seg * 4) * 4),
                               h_in + (size_t)c * 4096 + s64 * 32 + seg * 4);
                }
            }
            CP_COMMIT();

            const float* hb = HS + (kcc & 3) * HS_BUF;
#pragma unroll
            for (int sub = 0; sub < 2; sub++) {
                const int kcc32 = kcc * 2 + sub;
                const float* pa = hb + (sub * 64 + r0) * HS_STRIDE + tig * 8;
                const float* pb = hb + (sub * 64 + r0 + 8) * HS_STRIDE + tig * 8;
                float4 fA0 = *reinterpret_cast<const float4*>(pa);
                float4 fA1 = *reinterpret_cast<const float4*>(pa + 4);
                float4 fB0 = *reinterpret_cast<const float4*>(pb);
                float4 fB1 = *reinterpret_cast<const float4*>(pb + 4);
                float4 bA0 = FB4[((kcc32 * 4 + t0i) * 32 + lane) * 2 + 0];
                float4 bA1 = FB4[((kcc32 * 4 + t0i) * 32 + lane) * 2 + 1];
                float4 bB0 = FB4[((kcc32 * 4 + t1i) * 32 + lane) * 2 + 0];
                float4 bB1 = FB4[((kcc32 * 4 + t1i) * 32 + lane) * 2 + 1];
#pragma unroll
                for (int q = 0; q < 4; q++) {
                    unsigned a[4];
                    if (q == 0)      { a[0]=fu(fA0.x); a[1]=fu(fB0.x); a[2]=fu(fA0.y); a[3]=fu(fB0.y); }
                    else if (q == 1) { a[0]=fu(fA0.z); a[1]=fu(fB0.z); a[2]=fu(fA0.w); a[3]=fu(fB0.w); }
                    else if (q == 2) { a[0]=fu(fA1.x); a[1]=fu(fB1.x); a[2]=fu(fA1.y); a[3]=fu(fB1.y); }
                    else             { a[0]=fu(fA1.z); a[1]=fu(fB1.z); a[2]=fu(fA1.w); a[3]=fu(fB1.w); }
                    unsigned b0a, b1a, b0b, b1b;
                    if (q == 0)      { b0a = fu(bA0.x); b1a = fu(bA0.y); b0b = fu(bB0.x); b1b = fu(bB0.y); }
                    else if (q == 1) { b0a = fu(bA0.z); b1a = fu(bA0.w); b0b = fu(bB0.z); b1b = fu(bB0.w); }
                    else if (q == 2) { b0a = fu(bA1.x); b1a = fu(bA1.y); b0b = fu(bB1.x); b1b = fu(bB1.y); }
                    else             { b0a = fu(bA1.z); b1a = fu(bA1.w); b0b = fu(bB1.z); b1b = fu(bB1.w); }
                    mma_tf32(acc0, a, b0a, b1a);
                    mma_tf32(acc1, a, b0b, b1b);
                }
            }
        }
        __syncthreads();

        // gate exchange
#pragma unroll
        for (int j = 0; j < 4; j++) {
            int row = wm * 16 + gid + ((j >> 1) ? 8 : 0);
            GM[row * 33 + t0i * 8 + tig * 2 + (j & 1)] = acc0[j];
            GM[row * 33 + t1i * 8 + tig * 2 + (j & 1)] = acc1[j];
        }
        __syncthreads();

        // epilogue: gates + c/h update (xg from SMEM); h written in fragment layout
#pragma unroll
        for (int i = 0; i < 2; i++) {
            int e = tid + i * NTHR;
            int row = e >> 3, j = e & 7;
            float zi = GM[row * 33 + 0 * 8 + j] + XGS[row * 32 + 0 * 8 + j];
            float zf = GM[row * 33 + 1 * 8 + j] + XGS[row * 32 + 1 * 8 + j];
            float zg = GM[row * 33 + 2 * 8 + j] + XGS[row * 32 + 2 * 8 + j];
            float zo = GM[row * 33 + 3 * 8 + j] + XGS[row * 32 + 3 * 8 + j];

            float ig = fsig(zi);
            float fg = fsig(zf);
            float gg = ftanh(zg);
            float og = fsig(zo);

            creg[i] = fg * creg[i] + ig * gg;
            float hv = og * ftanh(creg[i]);
            if (t == TT - 1) {
                out[(size_t)row * UU + u0 + j] = hv;
            } else {
                int mv   = (blk & 3) * 2 + (j >> 2);
                int tigv = j & 3;
                h_out[(ch2 * 64 + row) * 32 + tigv * 8 + mv] = tfbits(hv);
            }
        }

        // publish completion
        __syncthreads();
        if (t + 1 < TT && tid == 0) {
            __threadfence();
            atomicExch(&g_flag[blk], (unsigned)(t + 1));
        }
    }
}

// ---------- launch (exactly 3 kernels: prep, xg, lstm) ----------
extern "C" void kernel_launch(void* const* d_in, const int* in_sizes, int n_in,
                              void* d_out, int out_size) {
    const float *x = nullptr, *h0 = nullptr, *c0 = nullptr;
    const float *Wx = nullptr, *Wh = nullptr, *bias = nullptr;
    for (int i = 0; i < n_in; i++) {
        const int s = in_sizes[i];
        const float* p = (const float*)d_in[i];
        if      (s == BB * TT * DD) x = p;
        else if (s == DD * G4)      Wx = p;
        else if (s == UU * G4)      Wh = p;
        else if (s == G4)           bias = p;
        else if (s == BB * UU)      { if (!h0) h0 = p; else c0 = p; }
    }

    const int XG_SMEM   = (4 * XA_ST + 4 * XB_ST) * 4;               // 108544
    const int LSTM_SMEM = (32768 + 4 * HS_BUF + 2048 + 64 * 33) * 4; // ~215KB

    static bool attr_set = false;
    if (!attr_set) {
        cudaFuncSetAttribute(xg_kernel,
                             cudaFuncAttributeMaxDynamicSharedMemorySize, XG_SMEM);
        cudaFuncSetAttribute(lstm_persistent,
                             cudaFuncAttributeMaxDynamicSharedMemorySize, LSTM_SMEM);
        attr_set = true;
    }

    prep<<<(DD * G4 + 255) / 256, 256>>>(h0, Wx);
    xg_kernel<<<dim3(G4 / 64, (BB * TT) / 128), 256, XG_SMEM>>>(x, bias);
    lstm_persistent<<<NBLK, NTHR, LSTM_SMEM>>>(Wh, c0, (float*)d_out);
}

// round 10
// speedup vs baseline: 2.6053x; 1.3242x over previous
#include <cuda_runtime.h>
#include <cstdint>
#include <math.h>

#define BB 64
#define TT 512
#define DD 512
#define UU 1024
#define G4 4096   // 4*UU
#define NBLK 128
#define NTHR 256

// Scratch (allocation-free rule: __device__ globals)
__device__ float g_xg[(size_t)TT * NBLK * BB * 32];  // [t][blk][row][g*8+j] = 512MB
__device__ float g_Wxtf[(size_t)DD * G4];            // tf32-rounded Wx (8MB)
// h ping-pong in FRAGMENT layout:
// gidx(u,row) = (((u>>6)*2 + ((u>>5)&1))*64 + row)*32 + (u&3)*8 + ((u&31)>>2)
__device__ float g_h[2 * BB * UU];
__device__ unsigned g_flag[NBLK];                    // per-block completed-step count

// ---------- helpers ----------
__device__ __forceinline__ unsigned f2tf(float x) {
    unsigned r;
    asm volatile("cvt.rna.tf32.f32 %0, %1;" : "=r"(r) : "f"(x));
    return r;
}
__device__ __forceinline__ float tfbits(float x) { return __uint_as_float(f2tf(x)); }
__device__ __forceinline__ unsigned fu(float x) { return __float_as_uint(x); }
__device__ __forceinline__ unsigned futf(float x) { return f2tf(x); }

__device__ __forceinline__ void mma_tf32(float d[4], const unsigned a[4], unsigned b0, unsigned b1) {
    asm volatile(
        "mma.sync.aligned.m16n8k8.row.col.f32.tf32.tf32.f32 "
        "{%0,%1,%2,%3}, {%4,%5,%6,%7}, {%8,%9}, {%0,%1,%2,%3};"
        : "+f"(d[0]), "+f"(d[1]), "+f"(d[2]), "+f"(d[3])
        : "r"(a[0]), "r"(a[1]), "r"(a[2]), "r"(a[3]), "r"(b0), "r"(b1));
}

__device__ __forceinline__ float fsig(float z) { return 1.f / (1.f + __expf(-z)); }
__device__ __forceinline__ float ftanh(float z) { return 2.f / (1.f + __expf(-2.f * z)) - 1.f; }

__device__ __forceinline__ void cp_async16(uint32_t s, const float* g) {
    asm volatile("cp.async.cg.shared.global [%0], [%1], 16;\n" :: "r"(s), "l"(g));
}
#define CP_COMMIT() asm volatile("cp.async.commit_group;\n" ::: "memory")
#define CP_WAIT(N)  asm volatile("cp.async.wait_group %0;\n" :: "n"(N) : "memory")
#define BAR64(id)   asm volatile("bar.sync %0, 64;" :: "r"((id) + 1) : "memory")

// fragment-layout index for h: u in [0,1024), row in [0,64)
__device__ __forceinline__ int h_gidx(int u, int row) {
    int chunk = u >> 6;
    int sub   = (u >> 5) & 1;
    int tig   = u & 3;
    int m     = (u & 31) >> 2;
    return (((chunk * 2 + sub) * 64) + row) * 32 + tig * 8 + m;
}

// ---------- Kernel 1: prep — tf32-round Wx; h0 -> g_h (fragment layout); clear flags ----------
__global__ void __launch_bounds__(256) prep(const float* __restrict__ h0,
                                            const float* __restrict__ Wx) {
    int idx = blockIdx.x * 256 + threadIdx.x;
    if (idx < DD * G4) g_Wxtf[idx] = tfbits(Wx[idx]);
    if (idx < BB * UU) {
        int row = idx >> 10;
        int u   = idx & (UU - 1);
        g_h[h_gidx(u, row)] = tfbits(h0[idx]);
    }
    if (idx < NBLK) g_flag[idx] = 0;
}

// ---------- Kernel 2: xg = x @ Wx + b (pipelined, 4-stage cp.async) — proven R9 ----------
#define XA_ST (128 * 36)   // 4608 floats per A stage
#define XB_ST (32 * 68)    // 2176 floats per B stage
__global__ void __launch_bounds__(256, 2) xg_kernel(const float* __restrict__ x,
                                                    const float* __restrict__ bias) {
    extern __shared__ float sm[];
    float* As = sm;               // 4 stages
    float* Bs = sm + 4 * XA_ST;   // 4 stages

    const int tid  = threadIdx.x;
    const int w    = tid >> 5;
    const int lane = tid & 31;
    const int gid  = lane >> 2;
    const int tig  = lane & 3;
    const int wm   = w >> 1;
    const int wn   = w & 1;

    const int m0 = blockIdx.y * 128;
    const int c0 = blockIdx.x * 64;

    const uint32_t as_base = (uint32_t)__cvta_generic_to_shared(As);
    const uint32_t bs_base = (uint32_t)__cvta_generic_to_shared(Bs);

    float acc[2][4][4];
#pragma unroll
    for (int mi = 0; mi < 2; mi++)
#pragma unroll
        for (int ni = 0; ni < 4; ni++)
#pragma unroll
            for (int j = 0; j < 4; j++) acc[mi][ni][j] = 0.f;

    auto issue = [&](int kc, int s) {
#pragma unroll
        for (int i = 0; i < 4; i++) {
            int id  = tid + i * 256;
            int row = id >> 3;
            int k4  = (id & 7) * 4;
            cp_async16(as_base + (uint32_t)((s * XA_ST + row * 36 + k4) * 4),
                       x + (size_t)(m0 + row) * DD + kc * 32 + k4);
        }
#pragma unroll
        for (int i = 0; i < 2; i++) {
            int id = tid + i * 256;
            int k  = id >> 4;
            int n4 = (id & 15) * 4;
            cp_async16(bs_base + (uint32_t)((s * XB_ST + k * 68 + n4) * 4),
                       g_Wxtf + (size_t)(kc * 32 + k) * G4 + c0 + n4);
        }
    };

    issue(0, 0); CP_COMMIT();
    issue(1, 1); CP_COMMIT();
    issue(2, 2); CP_COMMIT();

    for (int kc = 0; kc < 16; kc++) {
        CP_WAIT(2);
        __syncthreads();
        if (kc + 3 < 16) issue(kc + 3, (kc + 3) & 3);
        CP_COMMIT();

        const float* A = As + (kc & 3) * XA_ST;
        const float* B = Bs + (kc & 3) * XB_ST;
#pragma unroll
        for (int q = 0; q < 4; q++) {
            const int kk = q * 8 + tig;
            unsigned a[2][4];
#pragma unroll
            for (int mi = 0; mi < 2; mi++) {
                int r0 = wm * 32 + mi * 16 + gid;
                a[mi][0] = futf(A[r0 * 36 + kk]);
                a[mi][1] = futf(A[(r0 + 8) * 36 + kk]);
                a[mi][2] = futf(A[r0 * 36 + kk + 4]);
                a[mi][3] = futf(A[(r0 + 8) * 36 + kk + 4]);
            }
#pragma unroll
            for (int ni = 0; ni < 4; ni++) {
                int cb = wn * 32 + ni * 8 + gid;
                unsigned b0 = fu(B[kk * 68 + cb]);
                unsigned b1 = fu(B[(kk + 4) * 68 + cb]);
#pragma unroll
                for (int mi = 0; mi < 2; mi++) mma_tf32(acc[mi][ni], a[mi], b0, b1);
            }
        }
        __syncthreads();
    }

#pragma unroll
    for (int mi = 0; mi < 2; mi++) {
#pragma unroll
        for (int ni = 0; ni < 4; ni++) {
#pragma unroll
            for (int j = 0; j < 4; j++) {
                int m   = m0 + wm * 32 + mi * 16 + gid + ((j >= 2) ? 8 : 0);
                int col = c0 + wn * 32 + ni * 8 + tig * 2 + (j & 1);
                float v = acc[mi][ni][j] + bias[col];
                int b   = m >> 9;
                int t   = m & (TT - 1);
                int g   = col >> 10;
                int u   = col & (UU - 1);
                int blk = u >> 3;
                int jj  = u & 7;
                g_xg[(((size_t)t * NBLK + blk) * BB + b) * 32 + g * 8 + jj] = v;
            }
        }
    }
}

// ---------- Kernel 3: persistent LSTM, K-split-4 warp groups ----------
// 8 warps = 4 K-groups (kg = w>>1) x 2 row-halves (wm2 = w&1).
// Warp: rows wm2*32..+31, ALL 4 gate tiles, K-slice kcc32 in [8kg, 8kg+8).
// Per-kg private cp.async pipeline (2 sub-buffers, named barrier kg+1).
// Cross-kg reduction through GM (4 slices), aliased into the staging region.
#define SUB_FL 2304                 // 64 rows * 36 floats per staged sub
#define HSREG  (4 * 2 * SUB_FL)     // 18432 floats staging (aliased by GM after k-loop)
__global__ void __launch_bounds__(NTHR, 1) lstm_persistent(const float* __restrict__ Wh,
                                                           const float* __restrict__ c0,
                                                           float* __restrict__ out) {
    extern __shared__ float smem[];
    float* FB = smem;               // 32768 f: B-fragments (XOR-swizzled)
    float* HS = FB + 32768;         // 18432 f: staging; aliased as GM[4][64][33] post-loop
    float* GM = HS;

    const int tid  = threadIdx.x;
    const int w    = tid >> 5;
    const int lane = tid & 31;
    const int gid  = lane >> 2;
    const int tig  = lane & 3;
    const int kg   = w >> 1;        // K-group 0..3
    const int wm2  = w & 1;         // row half
    const int t64  = tid & 63;      // thread within kg's 64
    const int blk  = blockIdx.x;
    const int u0   = blk * 8;

    // one-time: Wh fragments (tf32), XOR-swizzled float4 placement:
    // physical = ((f*32+ln)*2 + ((e>>2) ^ (gid(ln)&1)))*4 + (e&3)
    for (int idx = tid; idx < 32768; idx += NTHR) {
        int e     = idx & 7;
        int ln    = (idx >> 3) & 31;
        int f     = idx >> 8;            // kcc32*4 + tile
        int q     = e >> 1;
        int pair  = e & 1;
        int lgid  = ln >> 2;
        int ltig  = ln & 3;
        int kcc32 = f >> 2;
        int tile  = f & 3;
        int k     = kcc32 * 32 + q * 8 + ltig + pair * 4;
        int pidx  = ((f * 32 + ln) * 2 + ((e >> 2) ^ (lgid & 1))) * 4 + (e & 3);
        FB[pidx] = tfbits(Wh[(size_t)k * G4 + tile * UU + u0 + lgid]);
    }

    float creg[2];
#pragma unroll
    for (int i = 0; i < 2; i++) {
        int e = tid + i * NTHR;
        int row = e >> 3, j = e & 7;
        creg[i] = c0[(size_t)row * UU + u0 + j];
    }
    __syncthreads();

    const float4* FB4 = reinterpret_cast<const float4*>(FB);
    const uint32_t hs_kg = (uint32_t)__cvta_generic_to_shared(HS) + (uint32_t)(kg * 2 * SUB_FL * 4);
    float* HSkg = HS + kg * 2 * SUB_FL;

    const int ch2 = (blk >> 3) * 2 + ((blk >> 2) & 1);   // epilogue h fragment constants
    volatile unsigned* vflag = (volatile unsigned*)g_flag;

    for (int t = 0; t < TT; t++) {
        const float* h_in = g_h + (size_t)(t & 1) * BB * UU;
        float* h_out      = g_h + (size_t)((t + 1) & 1) * BB * UU;
        const float* xgt  = g_xg + ((size_t)t * NBLK + blk) * (BB * 32);

        // ---- wait for ALL producers of h_t (single wide poll, proven) ----
        if (t > 0 && tid < NBLK) {
            while (vflag[tid] < (unsigned)t) { }
            __threadfence();
        }
        __syncthreads();   // also: epilogue GM reads (aliasing HS) done before restaging

        // xg prefetch into registers (consumed only in epilogue)
        float xr[2][4];
#pragma unroll
        for (int i = 0; i < 2; i++) {
            int e = tid + i * NTHR;
            int row = e >> 3, j = e & 7;
#pragma unroll
            for (int g = 0; g < 4; g++)
                xr[i][g] = __ldg(xgt + row * 32 + g * 8 + j);
        }

        float acc[2][4][4];
#pragma unroll
        for (int mt = 0; mt < 2; mt++)
#pragma unroll
            for (int tl = 0; tl < 4; tl++)
#pragma unroll
                for (int j = 0; j < 4; j++) acc[mt][tl][j] = 0.f;

        // per-kg staging lambda: sub s -> buffer s&1
        auto stage = [&](int s) {
            const float* src = h_in + (size_t)(kg * 8 + s) * 2048;
            uint32_t dst = hs_kg + (uint32_t)(((s & 1) * SUB_FL) * 4);
#pragma unroll
            for (int i = 0; i < 8; i++) {
                int id = i * 64 + t64;
                int row = id >> 3, seg = id & 7;
                cp_async16(dst + (uint32_t)((row * 36 + seg * 4) * 4),
                           src + row * 32 + seg * 4);
            }
        };

        stage(0); CP_COMMIT();
        stage(1); CP_COMMIT();

        for (int s = 0; s < 8; s++) {
            if (s < 7) { CP_WAIT(1); } else { CP_WAIT(0); }
            BAR64(kg);    // both warps of kg: sub s landed

            const float* buf = HSkg + (s & 1) * SUB_FL;
            const int kcc32 = kg * 8 + s;

            // A fragments for both mtiles: 8 LDS.128 (conflict-free)
            unsigned a[2][4][4];
#pragma unroll
            for (int mt = 0; mt < 2; mt++) {
                int r = wm2 * 32 + mt * 16 + gid;
                const float* pa = buf + r * 36 + tig * 8;
                const float* pb = buf + (r + 8) * 36 + tig * 8;
                float4 fA0 = *reinterpret_cast<const float4*>(pa);
                float4 fA1 = *reinterpret_cast<const float4*>(pa + 4);
                float4 fB0 = *reinterpret_cast<const float4*>(pb);
                float4 fB1 = *reinterpret_cast<const float4*>(pb + 4);
                a[mt][0][0] = fu(fA0.x); a[mt][0][1] = fu(fB0.x); a[mt][0][2] = fu(fA0.y); a[mt][0][3] = fu(fB0.y);
                a[mt][1][0] = fu(fA0.z); a[mt][1][1] = fu(fB0.z); a[mt][1][2] = fu(fA0.w); a[mt][1][3] = fu(fB0.w);
                a[mt][2][0] = fu(fA1.x); a[mt][2][1] = fu(fB1.x); a[mt][2][2] = fu(fA1.y); a[mt][2][3] = fu(fB1.y);
                a[mt][3][0] = fu(fA1.z); a[mt][3][1] = fu(fB1.z); a[mt][3][2] = fu(fA1.w); a[mt][3][3] = fu(fB1.w);
            }

#pragma unroll
            for (int tl = 0; tl < 4; tl++) {
                int bidx = ((kcc32 * 4 + tl) * 32 + lane) * 2;
                float4 b0v = FB4[bidx + (gid & 1)];        // logical first half
                float4 b1v = FB4[bidx + ((gid & 1) ^ 1)];  // logical second half
#pragma unroll
                for (int mt = 0; mt < 2; mt++) {
                    mma_tf32(acc[mt][tl], a[mt][0], fu(b0v.x), fu(b0v.y));
                    mma_tf32(acc[mt][tl], a[mt][1], fu(b0v.z), fu(b0v.w));
                    mma_tf32(acc[mt][tl], a[mt][2], fu(b1v.x), fu(b1v.y));
                    mma_tf32(acc[mt][tl], a[mt][3], fu(b1v.z), fu(b1v.w));
                }
            }

            BAR64(kg);    // both warps of kg done reading buffer s&1
            if (s + 2 < 8) { stage(s + 2); CP_COMMIT(); }
        }

        __syncthreads();  // all kgs done with HS -> safe to alias as GM

        // write partials: GM[kg][row][col], col = tile*8 + tig*2 + (j&1)
#pragma unroll
        for (int mt = 0; mt < 2; mt++)
#pragma unroll
            for (int tl = 0; tl < 4; tl++)
#pragma unroll
                for (int j = 0; j < 4; j++) {
                    int row = wm2 * 32 + mt * 16 + gid + ((j >> 1) ? 8 : 0);
                    int col = tl * 8 + tig * 2 + (j & 1);
                    GM[(kg * 64 + row) * 33 + col] = acc[mt][tl][j];
                }
        __syncthreads();

        // epilogue: sum 4 partials + xg, gates, c/h update
#pragma unroll
        for (int i = 0; i < 2; i++) {
            int e = tid + i * NTHR;
            int row = e >> 3, j = e & 7;
            float z[4];
#pragma unroll
            for (int g = 0; g < 4; g++) {
                float s = xr[i][g];
#pragma unroll
                for (int p = 0; p < 4; p++)
                    s += GM[(p * 64 + row) * 33 + g * 8 + j];
                z[g] = s;
            }
            float ig = fsig(z[0]);
            float fg = fsig(z[1]);
            float gg = ftanh(z[2]);
            float og = fsig(z[3]);

            creg[i] = fg * creg[i] + ig * gg;
            float hv = og * ftanh(creg[i]);
            if (t == TT - 1) {
                out[(size_t)row * UU + u0 + j] = hv;
            } else {
                int mv   = (blk & 3) * 2 + (j >> 2);
                int tigv = j & 3;
                h_out[(ch2 * 64 + row) * 32 + tigv * 8 + mv] = tfbits(hv);
            }
        }

        // publish completion
        __syncthreads();
        if (t + 1 < TT && tid == 0) {
            __threadfence();
            atomicExch(&g_flag[blk], (unsigned)(t + 1));
        }
    }
}

// ---------- launch (exactly 3 kernels: prep, xg, lstm) ----------
extern "C" void kernel_launch(void* const* d_in, const int* in_sizes, int n_in,
                              void* d_out, int out_size) {
    const float *x = nullptr, *h0 = nullptr, *c0 = nullptr;
    const float *Wx = nullptr, *Wh = nullptr, *bias = nullptr;
    for (int i = 0; i < n_in; i++) {
        const int s = in_sizes[i];
        const float* p = (const float*)d_in[i];
        if      (s == BB * TT * DD) x = p;
        else if (s == DD * G4)      Wx = p;
        else if (s == UU * G4)      Wh = p;
        else if (s == G4)           bias = p;
        else if (s == BB * UU)      { if (!h0) h0 = p; else c0 = p; }
    }

    const int XG_SMEM   = (4 * XA_ST + 4 * XB_ST) * 4;   // 108544
    const int LSTM_SMEM = (32768 + HSREG) * 4;           // 204800

    static bool attr_set = false;
    if (!attr_set) {
        cudaFuncSetAttribute(xg_kernel,
                             cudaFuncAttributeMaxDynamicSharedMemorySize, XG_SMEM);
        cudaFuncSetAttribute(lstm_persistent,
                             cudaFuncAttributeMaxDynamicSharedMemorySize, LSTM_SMEM);
        attr_set = true;
    }

    prep<<<(DD * G4 + 255) / 256, 256>>>(h0, Wx);
    xg_kernel<<<dim3(G4 / 64, (BB * TT) / 128), 256, XG_SMEM>>>(x, bias);
    lstm_persistent<<<NBLK, NTHR, LSTM_SMEM>>>(Wh, c0, (float*)d_out);
}